// round 7
// baseline (speedup 1.0000x reference)
#include <cuda_runtime.h>
#include <math_constants.h>

#define NPTS   8192
#define BATCH  4
#define KNN    4
#define QPB    224
#define SPLIT  4
#define THREADS (QPB * SPLIT)      // 896 threads = 28 warps
#define JPS    (NPTS / SPLIT)      // 2048 candidates per slice
#define G      16                  // candidates per filter group
#define GRPX   37                  // 37*4 = 148 blocks = 1 full wave

#define PTS_BYTES  (NPTS * 16)               // pair-interleaved point data, 128 KB
#define PART_N     (THREADS * KNN)           // 3584
#define SMEM_BYTES (PTS_BYTES + PART_N * 8)  // 159744 B

typedef unsigned long long u64;

// Packed fp32x2 ops (Blackwell; only reachable via PTX)
#define FMA2(d, a, b, c) asm("fma.rn.f32x2 %0, %1, %2, %3;" : "=l"(d) : "l"(a), "l"(b), "l"(c))
#define ADD2(d, a, b)    asm("add.rn.f32x2 %0, %1, %2;"     : "=l"(d) : "l"(a), "l"(b))
#define PACK2(d, lo, hi) asm("mov.b64 %0, {%1, %2};" : "=l"(d) : "r"(lo), "r"(hi))
#define UNPACK2(lo, hi, s) asm("mov.b64 {%0, %1}, %2;" : "=r"(lo), "=r"(hi) : "l"(s))

__device__ __forceinline__ void insert4(float sv, int j,
                                        float& v0, float& v1, float& v2, float& v3,
                                        int& i0, int& i1, int& i2, int& i3) {
    if (sv > v3) {
        if (sv > v2) {
            v3 = v2; i3 = i2;
            if (sv > v1) {
                v2 = v1; i2 = i1;
                if (sv > v0) {
                    v1 = v0; i1 = i0;
                    v0 = sv; i0 = j;
                } else { v1 = sv; i1 = j; }
            } else { v2 = sv; i2 = j; }
        } else { v3 = sv; i3 = j; }
    }
}

// Pair-interleaved layout, per 2 points (32 B): [x0 x1][y0 y1][z0 z1][nh0 nh1]
// float accessors: x(j)=bf[(j>>1)*8+(j&1)], y:+2, z:+4, nh:+6  (nh = -0.5*||p||^2)

__global__ __launch_bounds__(THREADS, 1)
void knn_gather_kernel(const float* __restrict__ x, float* __restrict__ out) {
    extern __shared__ char smem_raw[];
    float* __restrict__ bf  = (float*)smem_raw;                    // paired points
    float* __restrict__ pv  = (float*)(smem_raw + PTS_BYTES);      // [PART_N]
    int*   __restrict__ pix = (int*)  (smem_raw + PTS_BYTES + PART_N * 4);

    const int b = blockIdx.y;
    const float* __restrict__ xb = x + (size_t)b * NPTS * 3;

    // Stage: each thread builds one 2-point block.
    for (int j2 = threadIdx.x; j2 < NPTS / 2; j2 += THREADS) {
        const int ja = 2 * j2, jb = ja + 1;
        float ax = xb[3 * ja + 0], ay = xb[3 * ja + 1], az = xb[3 * ja + 2];
        float bx = xb[3 * jb + 0], by = xb[3 * jb + 1], bz = xb[3 * jb + 2];
        float anh = -0.5f * (ax * ax + ay * ay + az * az);
        float bnh = -0.5f * (bx * bx + by * by + bz * bz);
        float* d = bf + j2 * 8;
        d[0] = ax; d[1] = bx;
        d[2] = ay; d[3] = by;
        d[4] = az; d[5] = bz;
        d[6] = anh; d[7] = bnh;
    }
    __syncthreads();

    const int t     = threadIdx.x;
    const int qi    = t % QPB;        // warps never straddle (224 = 7 warps)
    const int slice = t / QPB;
    const int q     = blockIdx.x * QPB + qi;
    const bool active = (q < NPTS);

    float v0 = -CUDART_INF_F, v1 = -CUDART_INF_F, v2 = -CUDART_INF_F, v3 = -CUDART_INF_F;
    int   i0 = 0, i1 = 0, i2 = 0, i3 = 0;

    if (active) {
        const float qx = bf[(q >> 1) * 8 + (q & 1)];
        const float qy = bf[(q >> 1) * 8 + (q & 1) + 2];
        const float qz = bf[(q >> 1) * 8 + (q & 1) + 4];

        u64 qx2, qy2, qz2, nv32;
        {
            const unsigned ux = __float_as_uint(qx);
            const unsigned uy = __float_as_uint(qy);
            const unsigned uz = __float_as_uint(qz);
            PACK2(qx2, ux, ux);
            PACK2(qy2, uy, uy);
            PACK2(qz2, uz, uz);
            const unsigned un = __float_as_uint(-v3);   // +inf -> first group takes slow path
            PACK2(nv32, un, un);
        }

        const ulonglong2* __restrict__ pq = (const ulonglong2*)bf;  // 2 per point-pair
        const int jbase = slice * JPS;

        for (int j0 = jbase; j0 < jbase + JPS; j0 += G) {
            unsigned acc = 0xFFFFFFFFu;
            #pragma unroll
            for (int e = 0; e < G / 2; ++e) {
                const int j2 = (j0 >> 1) + e;
                const ulonglong2 qa = pq[j2 * 2 + 0];   // {x-pair, y-pair}  broadcast LDS.128
                const ulonglong2 qb = pq[j2 * 2 + 1];   // {z-pair, nh-pair}
                u64 u;
                FMA2(u, qx2, qa.x, qb.y);               // fma(qx, px, -h)   (lanewise, fp32-exact)
                FMA2(u, qy2, qa.y, u);
                FMA2(u, qz2, qb.x, u);
                u64 tt;
                ADD2(tt, u, nv32);                      // s - v3
                unsigned lo, hi;
                UNPACK2(lo, hi, tt);                    // free at SASS (register names)
                acc &= lo & hi;                         // single LOP3: AND of sign bits
            }
            // bit31(acc)=1 iff ALL s <= v3  ->  exact rejection, no epsilon.
            if ((int)acc >= 0) {
                #pragma unroll
                for (int e = 0; e < G; ++e) {
                    const int j = j0 + e;
                    const float* p = bf + (j >> 1) * 8 + (j & 1);
                    float u = __fmaf_rn(qx, p[0], p[6]);     // fma(qx, px, -h)
                    u       = __fmaf_rn(qy, p[2], u);
                    u       = __fmaf_rn(qz, p[4], u);
                    insert4(u, j, v0, v1, v2, v3, i0, i1, i2, i3);
                }
                const unsigned un = __float_as_uint(-v3);
                PACK2(nv32, un, un);
            }
        }
        const int base = t * KNN;
        pv[base + 0] = v0; pix[base + 0] = i0;
        pv[base + 1] = v1; pix[base + 1] = i1;
        pv[base + 2] = v2; pix[base + 2] = i2;
        pv[base + 3] = v3; pix[base + 3] = i3;
    }
    __syncthreads();

    // Merge slice partials (slice-ascending = j-ascending => stable, matches top_k).
    if (active && slice == 0) {
        float w0 = -CUDART_INF_F, w1 = -CUDART_INF_F, w2 = -CUDART_INF_F, w3 = -CUDART_INF_F;
        int   k0 = 0, k1 = 0, k2 = 0, k3 = 0;
        #pragma unroll
        for (int sl = 0; sl < SPLIT; ++sl) {
            const int base = (sl * QPB + qi) * KNN;
            #pragma unroll
            for (int e = 0; e < KNN; ++e)
                insert4(pv[base + e], pix[base + e], w0, w1, w2, w3, k0, k1, k2, k3);
        }

        float* __restrict__ o = out + (((size_t)b * NPTS + q) * KNN) * 3;
        const int ks[KNN] = {k0, k1, k2, k3};
        #pragma unroll
        for (int e = 0; e < KNN; ++e) {
            const float* p = bf + (ks[e] >> 1) * 8 + (ks[e] & 1);
            o[3 * e + 0] = p[0];
            o[3 * e + 1] = p[2];
            o[3 * e + 2] = p[4];
        }
    }
}

extern "C" void kernel_launch(void* const* d_in, const int* in_sizes, int n_in,
                              void* d_out, int out_size) {
    (void)n_in; (void)in_sizes; (void)out_size;
    const float* x = (const float*)d_in[0];
    float* out = (float*)d_out;

    cudaFuncSetAttribute(knn_gather_kernel,
                         cudaFuncAttributeMaxDynamicSharedMemorySize, SMEM_BYTES);

    dim3 grid(GRPX, BATCH, 1);   // 148 blocks = 1 full wave
    dim3 block(THREADS, 1, 1);   // 28 warps/SM
    knn_gather_kernel<<<grid, block, SMEM_BYTES>>>(x, out);
}

// round 8
// speedup vs baseline: 1.0283x; 1.0283x over previous
#include <cuda_runtime.h>
#include <math_constants.h>

#define NPTS   8192
#define BATCH  4
#define KNN    4
#define QPB    224
#define SPLIT  4
#define THREADS (QPB * SPLIT)      // 896 threads = 28 warps (reg cap 73/thread!)
#define JPS    (NPTS / SPLIT)      // 2048 candidates per slice
#define G      8                   // candidates per filter group (keep unroll small -> no spills)
#define GRPX   37                  // 37*4 = 148 blocks = 1 full wave

#define PTS_BYTES  (NPTS * 16)               // pair-interleaved point data, 128 KB
#define PART_N     (THREADS * KNN)           // 3584
#define SMEM_BYTES (PTS_BYTES + PART_N * 8)  // 159744 B

typedef unsigned long long u64;

// Packed fp32x2 ops (Blackwell; only reachable via PTX). Lanewise identical to scalar FFMA.
#define FMA2(d, a, b, c) asm("fma.rn.f32x2 %0, %1, %2, %3;" : "=l"(d) : "l"(a), "l"(b), "l"(c))
#define ADD2(d, a, b)    asm("add.rn.f32x2 %0, %1, %2;"     : "=l"(d) : "l"(a), "l"(b))
#define PACK2(d, lo, hi) asm("mov.b64 %0, {%1, %2};" : "=l"(d) : "r"(lo), "r"(hi))
#define UNPACK2(lo, hi, s) asm("mov.b64 {%0, %1}, %2;" : "=r"(lo), "=r"(hi) : "l"(s))

__device__ __forceinline__ void insert4(float sv, int j,
                                        float& v0, float& v1, float& v2, float& v3,
                                        int& i0, int& i1, int& i2, int& i3) {
    if (sv > v3) {
        if (sv > v2) {
            v3 = v2; i3 = i2;
            if (sv > v1) {
                v2 = v1; i2 = i1;
                if (sv > v0) {
                    v1 = v0; i1 = i0;
                    v0 = sv; i0 = j;
                } else { v1 = sv; i1 = j; }
            } else { v2 = sv; i2 = j; }
        } else { v3 = sv; i3 = j; }
    }
}

// Pair-interleaved layout, per 2 points (32 B): [x0 x1][y0 y1][z0 z1][nh0 nh1]
// scalar accessors: x(j)=bf[(j>>1)*8+(j&1)], y:+2, z:+4, nh:+6  (nh = -0.5||p||^2)

__global__ __launch_bounds__(THREADS, 1)
void knn_gather_kernel(const float* __restrict__ x, float* __restrict__ out) {
    extern __shared__ char smem_raw[];
    float* __restrict__ bf  = (float*)smem_raw;
    float* __restrict__ pv  = (float*)(smem_raw + PTS_BYTES);
    int*   __restrict__ pix = (int*)  (smem_raw + PTS_BYTES + PART_N * 4);

    const int b = blockIdx.y;
    const float* __restrict__ xb = x + (size_t)b * NPTS * 3;

    for (int j2 = threadIdx.x; j2 < NPTS / 2; j2 += THREADS) {
        const int ja = 2 * j2, jb = ja + 1;
        float ax = xb[3 * ja + 0], ay = xb[3 * ja + 1], az = xb[3 * ja + 2];
        float bx = xb[3 * jb + 0], by = xb[3 * jb + 1], bz = xb[3 * jb + 2];
        float* d = bf + j2 * 8;
        d[0] = ax; d[1] = bx;
        d[2] = ay; d[3] = by;
        d[4] = az; d[5] = bz;
        d[6] = -0.5f * (ax * ax + ay * ay + az * az);
        d[7] = -0.5f * (bx * bx + by * by + bz * bz);
    }
    __syncthreads();

    const int t     = threadIdx.x;
    const int qi    = t % QPB;        // warps never straddle (224 = 7 warps)
    const int slice = t / QPB;
    const int q     = blockIdx.x * QPB + qi;
    const bool active = (q < NPTS);

    float v0 = -CUDART_INF_F, v1 = -CUDART_INF_F, v2 = -CUDART_INF_F, v3 = -CUDART_INF_F;
    int   i0 = 0, i1 = 0, i2 = 0, i3 = 0;

    if (active) {
        const float qx = bf[(q >> 1) * 8 + (q & 1)];
        const float qy = bf[(q >> 1) * 8 + (q & 1) + 2];
        const float qz = bf[(q >> 1) * 8 + (q & 1) + 4];

        u64 qx2, qy2, qz2, nv32;
        {
            const unsigned ux = __float_as_uint(qx);
            const unsigned uy = __float_as_uint(qy);
            const unsigned uz = __float_as_uint(qz);
            PACK2(qx2, ux, ux);
            PACK2(qy2, uy, uy);
            PACK2(qz2, uz, uz);
            const unsigned un = __float_as_uint(-v3);   // +inf -> first group verified
            PACK2(nv32, un, un);
        }

        const ulonglong2* __restrict__ pw = (const ulonglong2*)bf + (size_t)slice * (JPS / 2) * 2;

        for (int j0 = slice * JPS; j0 < slice * JPS + JPS; j0 += G) {
            unsigned acc = 0xFFFFFFFFu;
            #pragma unroll
            for (int e = 0; e < G / 2; ++e) {
                const ulonglong2 qa = pw[2 * e + 0];    // {x-pair, y-pair}  broadcast LDS.128
                const ulonglong2 qb = pw[2 * e + 1];    // {z-pair, nh-pair}
                u64 u;
                FMA2(u, qx2, qa.x, qb.y);               // fma(qx, px, -h)  (fp32-exact per lane)
                FMA2(u, qy2, qa.y, u);
                FMA2(u, qz2, qb.x, u);
                u64 tt;
                ADD2(tt, u, nv32);                      // s - v3
                unsigned lo, hi;
                UNPACK2(lo, hi, tt);                    // register-name split, free in SASS
                acc &= lo & hi;                         // 1 LOP3: AND of sign bits
            }
            pw += G;                                    // G/2 pairs * 2 u64x2 each
            // sign(acc)=1 iff every s <= v3 -> exact rejection, zero false negatives.
            if ((int)acc >= 0) {
                #pragma unroll 1
                for (int e = 0; e < G; ++e) {
                    const int j = j0 + e;
                    const float* p = bf + (j >> 1) * 8 + (j & 1);
                    float u = __fmaf_rn(qx, p[0], p[6]);
                    u       = __fmaf_rn(qy, p[2], u);
                    u       = __fmaf_rn(qz, p[4], u);
                    insert4(u, j, v0, v1, v2, v3, i0, i1, i2, i3);
                }
                const unsigned un = __float_as_uint(-v3);
                PACK2(nv32, un, un);
            }
        }
        const int base = t * KNN;
        pv[base + 0] = v0; pix[base + 0] = i0;
        pv[base + 1] = v1; pix[base + 1] = i1;
        pv[base + 2] = v2; pix[base + 2] = i2;
        pv[base + 3] = v3; pix[base + 3] = i3;
    }
    __syncthreads();

    // Merge slice partials (slice-ascending = j-ascending => stable, matches top_k).
    if (active && slice == 0) {
        float w0 = -CUDART_INF_F, w1 = -CUDART_INF_F, w2 = -CUDART_INF_F, w3 = -CUDART_INF_F;
        int   k0 = 0, k1 = 0, k2 = 0, k3 = 0;
        #pragma unroll
        for (int sl = 0; sl < SPLIT; ++sl) {
            const int base = (sl * QPB + qi) * KNN;
            #pragma unroll
            for (int e = 0; e < KNN; ++e)
                insert4(pv[base + e], pix[base + e], w0, w1, w2, w3, k0, k1, k2, k3);
        }

        float* __restrict__ o = out + (((size_t)b * NPTS + q) * KNN) * 3;
        const int ks[KNN] = {k0, k1, k2, k3};
        #pragma unroll
        for (int e = 0; e < KNN; ++e) {
            const float* p = bf + (ks[e] >> 1) * 8 + (ks[e] & 1);
            o[3 * e + 0] = p[0];
            o[3 * e + 1] = p[2];
            o[3 * e + 2] = p[4];
        }
    }
}

extern "C" void kernel_launch(void* const* d_in, const int* in_sizes, int n_in,
                              void* d_out, int out_size) {
    (void)n_in; (void)in_sizes; (void)out_size;
    const float* x = (const float*)d_in[0];
    float* out = (float*)d_out;

    cudaFuncSetAttribute(knn_gather_kernel,
                         cudaFuncAttributeMaxDynamicSharedMemorySize, SMEM_BYTES);

    dim3 grid(GRPX, BATCH, 1);   // 148 blocks = 1 full wave
    dim3 block(THREADS, 1, 1);   // 28 warps/SM
    knn_gather_kernel<<<grid, block, SMEM_BYTES>>>(x, out);
}